// round 3
// baseline (speedup 1.0000x reference)
#include <cuda_runtime.h>
#include <cstdint>

// Problem constants (MB_projection: B=1024, IN=1024, EXP=40, K=7)
#define B_TOTAL   1024
#define IN_DIM    1024
#define OUT_DIM   40960
#define KNZ       7

// Tiling
#define O_CTA     1024          // outputs per CTA (blockIdx.x: 40 tiles)
#define BC        32            // batch rows per CTA (blockIdx.y: 32 tiles)
#define NTHREADS  512
#define NWARPS    16
#define O_WARP    8             // outputs per warp per pass
#define O_PASS    (NWARPS * O_WARP)   // 128 outputs per CTA pass
#define NPASS     (O_CTA / O_PASS)    // 8

#define XS_STRIDE 1025          // pad: gather bank = (lane + idx) % 32, conflict-free
#define ST_STRIDE 132           // pad: STS.128 start bank 4*lane, LDS.128 row read conflict-free

// smem word layout
#define XS_WORDS   (BC * XS_STRIDE)            // 32800
#define META_WORDS (O_CTA * 16)                // 16384
#define ST_WORDS   (BC * ST_STRIDE)            // 4224
#define SMEM_WORDS (XS_WORDS + META_WORDS + ST_WORDS)   // 53408
#define SMEM_BYTES (SMEM_WORDS * 4)            // 213,632 B (< 227 KB limit)

// Packed metadata: per output o, 16 u32 words: (idx0,val0,idx1,val1,...,idx6,val6,pad,pad)
// 64B-aligned so the main kernel reads it as 4 broadcast LDS.128.
__device__ uint4 g_packed[OUT_DIM * 4];   // 2.62 MB static scratch

__global__ void pack_kernel(const int* __restrict__ idx, const float* __restrict__ vals) {
    int m = blockIdx.x * blockDim.x + threadIdx.x;   // flat element index, coalesced reads
    if (m >= OUT_DIM * KNZ) return;
    int o = m / KNZ;
    int k = m - o * KNZ;
    unsigned int* p = reinterpret_cast<unsigned int*>(g_packed);
    p[o * 16 + 2 * k]     = (unsigned int)idx[m];
    p[o * 16 + 2 * k + 1] = __float_as_uint(vals[m]);
}

__global__ __launch_bounds__(NTHREADS, 1)
void mb_proj_kernel(const float* __restrict__ x, float* __restrict__ y) {
    extern __shared__ unsigned int smem[];
    float*        xs    = reinterpret_cast<float*>(smem);                 // [BC][XS_STRIDE]
    unsigned int* meta  = smem + XS_WORDS;                                // [O_CTA][16]
    float*        stage = reinterpret_cast<float*>(smem + XS_WORDS + META_WORDS); // [BC][ST_STRIDE]

    const int t    = threadIdx.x;
    const int lane = t & 31;
    const int w    = t >> 5;
    const int o_cta = blockIdx.x * O_CTA;
    const int b0    = blockIdx.y * BC;

    // ---- Load packed metadata for this output tile (coalesced LDG.128 -> STS.128) ----
    {
        const uint4* src = g_packed + (size_t)blockIdx.x * (O_CTA * 4);
        uint4* dst = reinterpret_cast<uint4*>(meta);
        #pragma unroll
        for (int i = 0; i < (O_CTA * 4) / NTHREADS; ++i)   // 8 iters
            dst[t + i * NTHREADS] = src[t + i * NTHREADS];
    }

    // ---- Load x batch tile: row r by 16 threads, float4 coalesced LDG, scalar STS ----
    {
        const int r  = t >> 4;          // 0..31
        const int c4 = t & 15;          // float4 lane within row
        const float4* xrow = reinterpret_cast<const float4*>(x + (size_t)(b0 + r) * IN_DIM);
        float* xsr = xs + r * XS_STRIDE;
        #pragma unroll
        for (int i = 0; i < IN_DIM / 64; ++i) {            // 16 iters
            float4 v = xrow[c4 + i * 16];
            int c = (c4 + i * 16) * 4;
            xsr[c + 0] = v.x; xsr[c + 1] = v.y; xsr[c + 2] = v.z; xsr[c + 3] = v.w;
        }
    }
    __syncthreads();

    const float* xb = xs + lane * XS_STRIDE;   // per-lane gather base (lane = batch row)

    for (int p = 0; p < NPASS; ++p) {
        const int obase = p * O_PASS + w * O_WARP;   // this warp's first o_local

        // ---- Compute: 8 outputs per warp, 32 batch rows (lane=b), idx uniform per instr ----
        #pragma unroll
        for (int g = 0; g < 2; ++g) {
            float acc[4];
            #pragma unroll
            for (int e = 0; e < 4; ++e) {
                const int ol = obase + g * 4 + e;
                const uint4* mp = reinterpret_cast<const uint4*>(meta + ol * 16);
                uint4 m0 = mp[0], m1 = mp[1], m2 = mp[2], m3 = mp[3];  // 4 broadcast LDS.128
                // 7 conflict-free gather LDS.32, two independent FMA chains
                float a0 = __uint_as_float(m0.y) * xb[m0.x];
                float a1 = __uint_as_float(m0.w) * xb[m0.z];
                a0 += __uint_as_float(m1.y) * xb[m1.x];
                a1 += __uint_as_float(m1.w) * xb[m1.z];
                a0 += __uint_as_float(m2.y) * xb[m2.x];
                a1 += __uint_as_float(m2.w) * xb[m2.z];
                a0 += __uint_as_float(m3.y) * xb[m3.x];    // k=6 (m3.z/.w are pad, unread)
                acc[e] = a0 + a1;
            }
            // Staging write: STS.128, start bank = (4*lane + off) % 32 -> conflict-free
            float4* sp = reinterpret_cast<float4*>(stage + lane * ST_STRIDE + (w * O_WARP + g * 4));
            *sp = make_float4(acc[0], acc[1], acc[2], acc[3]);
        }
        __syncthreads();

        // ---- Store: one warp per staged row -> 512B coalesced STG.128 per warp ----
        #pragma unroll
        for (int s = 0; s < 2; ++s) {
            const int b = w + 16 * s;
            float4 v = *reinterpret_cast<const float4*>(stage + b * ST_STRIDE + lane * 4);
            size_t off = (size_t)(b0 + b) * OUT_DIM + (size_t)(o_cta + p * O_PASS) + lane * 4;
            *reinterpret_cast<float4*>(y + off) = v;
        }
        __syncthreads();   // stage reused next pass
    }
}

extern "C" void kernel_launch(void* const* d_in, const int* in_sizes, int n_in,
                              void* d_out, int out_size) {
    const float* x    = (const float*)d_in[0];   // [B, IN] f32
    const float* vals = (const float*)d_in[1];   // [OUT, K] f32
    const int*   idx  = (const int*)d_in[2];     // [OUT, K] i32
    float*       y    = (float*)d_out;           // [B, OUT] f32

    // Pack (idx,val) pairs into 64B-aligned records (runs inside the graph; ~2 us)
    {
        const int total = OUT_DIM * KNZ;
        pack_kernel<<<(total + 255) / 256, 256>>>(idx, vals);
    }

    // Opt-in to 213.6 KB dynamic smem (idempotent; safe during capture)
    cudaFuncSetAttribute(mb_proj_kernel, cudaFuncAttributeMaxDynamicSharedMemorySize, SMEM_BYTES);

    dim3 grid(OUT_DIM / O_CTA, B_TOTAL / BC);    // (40, 32) = 1280 CTAs ~ 8.6 waves
    mb_proj_kernel<<<grid, NTHREADS, SMEM_BYTES>>>(x, y);
}

// round 5
// speedup vs baseline: 1.3692x; 1.3692x over previous
#include <cuda_runtime.h>
#include <cuda_fp16.h>
#include <cstdint>

// Problem constants (MB_projection: B=1024, IN=1024, EXP=40, K=7)
#define B_TOTAL   1024
#define IN_DIM    1024
#define OUT_DIM   40960
#define KNZ       7

// Tiling
#define BC        64            // batch rows per CTA (as 32 half2-packed pairs)
#define J32       32            // row-pairs per CTA
#define O_CTA     1024          // outputs per CTA
#define NTHREADS  512
#define NWARPS    16
#define O_WARP    8
#define O_PASS    (NWARPS * O_WARP)    // 128
#define NPASS     (O_CTA / O_PASS)     // 8

// smem word layout
#define XS_WORDS   (IN_DIM * J32)      // 32768  (half2 per word) = 128 KB
#define META_WORDS (O_CTA * 12)        // 12288  (3 uint4 per output) = 48 KB
#define ST_WORDS   (BC * 128)          // 8192   (xor-swizzled stage) = 32 KB
#define SMEM_BYTES ((XS_WORDS + META_WORDS + ST_WORDS) * 4)   // 212,992 B

// Packed metadata per output (48 B = 3 uint4):
//   m0 = {i0|i1<<16, i2|i3<<16, i4|i5<<16, i6}   (u16 indices)
//   m1 = {v0, v1, v2, v3}  m2 = {v4, v5, v6, pad}  (f32 vals)
__device__ uint4   g_meta[OUT_DIM * 3];              // ~2 MB
// x pre-transposed + fp16-packed: g_xt[c * B/2 + b2] = (x[2*b2][c], x[2*b2+1][c])
__device__ __half2 g_xt[IN_DIM * (B_TOTAL / 2)];     // 2 MB

__global__ void pack_kernel(const int* __restrict__ idx, const float* __restrict__ vals) {
    int o = blockIdx.x * blockDim.x + threadIdx.x;
    if (o >= OUT_DIM) return;
    const int*   ip = idx  + o * KNZ;
    const float* vp = vals + o * KNZ;
    uint4 m0, m1, m2;
    m0.x = (unsigned)ip[0] | ((unsigned)ip[1] << 16);
    m0.y = (unsigned)ip[2] | ((unsigned)ip[3] << 16);
    m0.z = (unsigned)ip[4] | ((unsigned)ip[5] << 16);
    m0.w = (unsigned)ip[6];
    m1.x = __float_as_uint(vp[0]); m1.y = __float_as_uint(vp[1]);
    m1.z = __float_as_uint(vp[2]); m1.w = __float_as_uint(vp[3]);
    m2.x = __float_as_uint(vp[4]); m2.y = __float_as_uint(vp[5]);
    m2.z = __float_as_uint(vp[6]); m2.w = 0u;
    g_meta[o * 3 + 0] = m0;
    g_meta[o * 3 + 1] = m1;
    g_meta[o * 3 + 2] = m2;
}

// Tiled transpose + fp16 pack: x[B][IN] f32 -> g_xt[IN][B/2] half2
__global__ void xt_kernel(const float* __restrict__ x) {
    __shared__ float tile[64][33];
    const int c0 = blockIdx.x * 32;
    const int r0 = blockIdx.y * 64;
    const int tx = threadIdx.x;   // 0..31
    const int ty = threadIdx.y;   // 0..7
    #pragma unroll
    for (int i = 0; i < 8; ++i)   // coalesced loads
        tile[ty + 8 * i][tx] = x[(size_t)(r0 + ty + 8 * i) * IN_DIM + c0 + tx];
    __syncthreads();
    #pragma unroll
    for (int i = 0; i < 4; ++i) {
        int c = ty + 8 * i;
        float lo = tile[2 * tx + 0][c];
        float hi = tile[2 * tx + 1][c];
        g_xt[(size_t)(c0 + c) * (B_TOTAL / 2) + (r0 >> 1) + tx] = __floats2half2_rn(lo, hi);
    }
}

__global__ __launch_bounds__(NTHREADS, 1)
void mb_proj_kernel(float* __restrict__ y) {
    extern __shared__ unsigned int smem[];
    __half2*      xs    = reinterpret_cast<__half2*>(smem);           // [IN][32] half2
    uint4*        meta  = reinterpret_cast<uint4*>(smem + XS_WORDS);  // [O_CTA][3]
    float*        stage = reinterpret_cast<float*>(smem + XS_WORDS + META_WORDS); // swizzled [64][128]

    const int t     = threadIdx.x;
    const int lane  = t & 31;
    const int w     = t >> 5;
    const int o_cta = blockIdx.x * O_CTA;
    const int b0    = blockIdx.y * BC;

    // ---- meta fill: coalesced LDG.128 -> STS.128 ----
    {
        const uint4* src = g_meta + (size_t)blockIdx.x * (O_CTA * 3);
        #pragma unroll
        for (int i = 0; i < (O_CTA * 3) / NTHREADS; ++i)   // 6 iters
            meta[t + i * NTHREADS] = src[t + i * NTHREADS];
    }
    // ---- x tile fill: uint4 (=4 half2) coalesced LDG.128 -> conflict-free STS.128 ----
    {
        const uint4* xsrc  = reinterpret_cast<const uint4*>(g_xt);
        uint4*       xdst  = reinterpret_cast<uint4*>(xs);
        const int    jq    = t & 7;           // uint4 slot within 32-half2 row (0..7)
        const int    cbase = t >> 3;          // 0..63
        const int    boff  = b0 >> 3;         // uint4 offset of batch window in xt row
        #pragma unroll
        for (int i = 0; i < 16; ++i) {
            int c = cbase + 64 * i;
            xdst[c * 8 + jq] = xsrc[(size_t)c * 128 + boff + jq];
        }
    }
    __syncthreads();

    const __half2* xb = xs + lane;   // lane = row-pair index j; gather bank = lane (conflict-free)

    for (int p = 0; p < NPASS; ++p) {
        const int obase = p * O_PASS + w * O_WARP;

        #pragma unroll
        for (int g = 0; g < 2; ++g) {
            float ax[4], ay[4];   // .x -> row 2*lane, .y -> row 2*lane+1
            #pragma unroll
            for (int e = 0; e < 4; ++e) {
                const uint4* mp = meta + (obase + g * 4 + e) * 3;
                uint4 m0 = mp[0], m1 = mp[1], m2 = mp[2];   // 3 broadcast LDS.128
                int i0 = m0.x & 0xFFFF, i1 = m0.x >> 16;
                int i2 = m0.y & 0xFFFF, i3 = m0.y >> 16;
                int i4 = m0.z & 0xFFFF, i5 = m0.z >> 16;
                int i6 = m0.w & 0xFFFF;
                // 7 conflict-free LDS.32 gathers, each serving 2 batch rows
                float2 x0 = __half22float2(xb[i0 * J32]);
                float2 x1 = __half22float2(xb[i1 * J32]);
                float2 x2 = __half22float2(xb[i2 * J32]);
                float2 x3 = __half22float2(xb[i3 * J32]);
                float2 x4 = __half22float2(xb[i4 * J32]);
                float2 x5 = __half22float2(xb[i5 * J32]);
                float2 x6 = __half22float2(xb[i6 * J32]);
                float v0 = __uint_as_float(m1.x), v1 = __uint_as_float(m1.y);
                float v2 = __uint_as_float(m1.z), v3 = __uint_as_float(m1.w);
                float v4 = __uint_as_float(m2.x), v5 = __uint_as_float(m2.y);
                float v6 = __uint_as_float(m2.z);
                // two independent FMA chains per row
                float sx = v0 * x0.x, tx2 = v1 * x1.x;
                float sy = v0 * x0.y, ty2 = v1 * x1.y;
                sx  = fmaf(v2, x2.x, sx);  tx2 = fmaf(v3, x3.x, tx2);
                sy  = fmaf(v2, x2.y, sy);  ty2 = fmaf(v3, x3.y, ty2);
                sx  = fmaf(v4, x4.x, sx);  tx2 = fmaf(v5, x5.x, tx2);
                sy  = fmaf(v4, x4.y, sy);  ty2 = fmaf(v5, x5.y, ty2);
                sx  = fmaf(v6, x6.x, sx);
                sy  = fmaf(v6, x6.y, sy);
                ax[e] = sx + tx2;
                ay[e] = sy + ty2;
            }
            // XOR-swizzled stage writes: both STS.128 conflict-free
            const int cc = w * O_WARP + g * 4;
            const int sz = (lane & 7) << 2;               // (row>>1)&7 == lane&7
            const int w0 = ((2 * lane) * 128 + cc) ^ sz;
            const int w1 = ((2 * lane + 1) * 128 + cc) ^ sz;
            *reinterpret_cast<float4*>(stage + w0) = make_float4(ax[0], ax[1], ax[2], ax[3]);
            *reinterpret_cast<float4*>(stage + w1) = make_float4(ay[0], ay[1], ay[2], ay[3]);
        }
        __syncthreads();

        // ---- Store: 4 rows per warp, conflict-free LDS.128 -> 512B coalesced STG.128 ----
        #pragma unroll
        for (int s = 0; s < 4; ++s) {
            const int r  = w * 4 + s;
            const int wd = (r * 128 + 4 * lane) ^ ((((r >> 1) & 7)) << 2);
            float4 v = *reinterpret_cast<const float4*>(stage + wd);
            size_t off = (size_t)(b0 + r) * OUT_DIM + (size_t)(o_cta + p * O_PASS) + 4 * lane;
            *reinterpret_cast<float4*>(y + off) = v;
        }
        __syncthreads();   // stage reused next pass
    }
}

extern "C" void kernel_launch(void* const* d_in, const int* in_sizes, int n_in,
                              void* d_out, int out_size) {
    const float* x    = (const float*)d_in[0];   // [B, IN] f32
    const float* vals = (const float*)d_in[1];   // [OUT, K] f32
    const int*   idx  = (const int*)d_in[2];     // [OUT, K] i32
    float*       y    = (float*)d_out;           // [B, OUT] f32

    pack_kernel<<<(OUT_DIM + 255) / 256, 256>>>(idx, vals);

    dim3 tb(32, 8);
    dim3 tg(IN_DIM / 32, B_TOTAL / 64);          // (32, 16)
    xt_kernel<<<tg, tb>>>(x);

    cudaFuncSetAttribute(mb_proj_kernel, cudaFuncAttributeMaxDynamicSharedMemorySize, SMEM_BYTES);
    dim3 grid(OUT_DIM / O_CTA, B_TOTAL / BC);    // (40, 16) = 640 CTAs
    mb_proj_kernel<<<grid, NTHREADS, SMEM_BYTES>>>(y);
}